// round 11
// baseline (speedup 1.0000x reference)
#include <cuda_runtime.h>
#include <cstddef>

#define NB 128
#define HS 33  // h row stride in float2 (odd -> conflict-free multi-row access)

__device__ float g_xp[(size_t)512 * 64 * 4096];  // [t][b][pcol]
__device__ float g_wxh[512 * 4096];              // [k][pcol], pcol=j*4+gate
__device__ float g_whh[1024 * 4096];
__device__ float g_bias[4096];
__device__ float g_h[2][64 * 1024];
__device__ unsigned g_cnt;

__device__ __forceinline__ void ffma2(unsigned long long &a, unsigned long long x,
                                      unsigned long long y) {
    asm volatile("fma.rn.f32x2 %0, %1, %2, %0;" : "+l"(a) : "l"(x), "l"(y));
}
__device__ __forceinline__ unsigned long long pk(float x, float y) {
    unsigned long long r;
    asm("mov.b64 %0,{%1,%2};" : "=l"(r) : "f"(x), "f"(y));
    return r;
}
__device__ __forceinline__ void upk(unsigned long long v, float &x, float &y) {
    asm("mov.b64 {%0,%1},%2;" : "=f"(x), "=f"(y) : "l"(v));
}
__device__ __forceinline__ float sigm(float x) { return 1.f / (1.f + expf(-x)); }

// ---------------- pack: permute weights to pcol = j*4+gate; reset state ----------------
__global__ void pack_kernel(const float *__restrict__ wxh, const float *__restrict__ whh,
                            const float *__restrict__ bias) {
    int stride = gridDim.x * blockDim.x;
    int i0 = blockIdx.x * blockDim.x + threadIdx.x;
    for (int idx = i0; idx < 1024 * 4096; idx += stride) {
        int k = idx >> 12, pcol = idx & 4095;
        int src = ((pcol & 3) << 10) + (pcol >> 2);  // gate*1024 + j
        g_whh[idx] = whh[(size_t)k * 4096 + src];
        if (k < 512) g_wxh[idx] = wxh[(size_t)k * 4096 + src];
        if (k == 0) g_bias[pcol] = bias[src];
    }
    for (int idx = i0; idx < 2 * 64 * 1024; idx += stride) (&g_h[0][0])[idx] = 0.f;
    if (i0 == 0) g_cnt = 0u;
}

// ---------------- projection: g_xp[t][b][:] = X[b,t,:] @ Wp + bias ----------------
__global__ void __launch_bounds__(256, 2) proj_kernel(const float *__restrict__ X) {
    __shared__ float As[2][16][66];
    __shared__ float Bs[2][16][132];
    int tid = threadIdx.x;
    int tx = tid & 15, ty = tid >> 4;
    int n0 = blockIdx.x * 128, m0 = blockIdx.y * 64;

    unsigned long long acc[4][4];
#pragma unroll
    for (int i = 0; i < 4; ++i)
#pragma unroll
        for (int q = 0; q < 4; ++q) acc[i][q] = 0ull;

    int am = tid >> 2, ak = (tid & 3) << 2;
    int bk = tid >> 5, bc = (tid & 31) << 2;

    float4 Av, Bv0, Bv1;
    Av = *(const float4 *)(X + (size_t)(m0 + am) * 512 + ak);
    Bv0 = *(const float4 *)(g_wxh + (size_t)bk * 4096 + n0 + bc);
    Bv1 = *(const float4 *)(g_wxh + (size_t)(bk + 8) * 4096 + n0 + bc);
    As[0][ak + 0][am] = Av.x; As[0][ak + 1][am] = Av.y;
    As[0][ak + 2][am] = Av.z; As[0][ak + 3][am] = Av.w;
    *(float4 *)&Bs[0][bk][bc] = Bv0;
    *(float4 *)&Bs[0][bk + 8][bc] = Bv1;
    __syncthreads();

    for (int kt = 0; kt < 32; ++kt) {
        int cur = kt & 1;
        if (kt < 31) {
            int kb = (kt + 1) << 4;
            Av = *(const float4 *)(X + (size_t)(m0 + am) * 512 + kb + ak);
            Bv0 = *(const float4 *)(g_wxh + (size_t)(kb + bk) * 4096 + n0 + bc);
            Bv1 = *(const float4 *)(g_wxh + (size_t)(kb + bk + 8) * 4096 + n0 + bc);
        }
#pragma unroll
        for (int k = 0; k < 16; ++k) {
            unsigned long long a[4], b[4];
#pragma unroll
            for (int i = 0; i < 4; ++i) {
                float av = As[cur][k][(ty << 2) + i];
                a[i] = pk(av, av);
            }
#pragma unroll
            for (int q = 0; q < 4; ++q)
                b[q] = *(const unsigned long long *)&Bs[cur][k][2 * tx + 32 * q];
#pragma unroll
            for (int i = 0; i < 4; ++i)
#pragma unroll
                for (int q = 0; q < 4; ++q) ffma2(acc[i][q], a[i], b[q]);
        }
        if (kt < 31) {
            int nb = cur ^ 1;
            As[nb][ak + 0][am] = Av.x; As[nb][ak + 1][am] = Av.y;
            As[nb][ak + 2][am] = Av.z; As[nb][ak + 3][am] = Av.w;
            *(float4 *)&Bs[nb][bk][bc] = Bv0;
            *(float4 *)&Bs[nb][bk + 8][bc] = Bv1;
        }
        __syncthreads();
    }

    float2 bb[4];
#pragma unroll
    for (int q = 0; q < 4; ++q) bb[q] = *(const float2 *)&g_bias[n0 + 2 * tx + 32 * q];
#pragma unroll
    for (int i = 0; i < 4; ++i) {
        int m = m0 + (ty << 2) + i;
        int t = m & 511, b = m >> 9;
        size_t base = ((size_t)t * 64 + b) * 4096 + n0 + 2 * tx;
#pragma unroll
        for (int q = 0; q < 4; ++q) {
            float lo, hi;
            upk(acc[i][q], lo, hi);
            *(float2 *)&g_xp[base + 32 * q] = make_float2(lo + bb[q].x, hi + bb[q].y);
        }
    }
}

// ---------------- persistent recurrence: 128 blocks x 256 threads ----------------
// Block p owns j in [8p,8p+8). Thread (rp 0..31, jp 0..7): rows {2rp,2rp+1}, one j
// (all 4 gates). 2 warps/SMSP for latency hiding. W slice resident in SMEM; h
// double-buffered in 64-k chunks; c-state in registers; 1 grid barrier/step.
__global__ void __launch_bounds__(256, 1)
recur_kernel(const float *__restrict__ scale, const float *__restrict__ offs,
             const float *__restrict__ mean, const float *__restrict__ var,
             float *__restrict__ out) {
    extern __shared__ float2 sm[];
    float2 *sW = sm;           // 512 kp * 32 = 16384 float2 (128 KB)
    float2 *sH = sm + 16384;   // 2 x 64*HS float2

    int tid = threadIdx.x, p = blockIdx.x;
    int jp = tid & 7, rp = tid >> 3;  // rp 0..31
    int r0 = rp << 1, r1 = r0 + 1;
    int j = (p << 3) + jp;

    // W_HH slice -> SMEM once, K-paired: sW[kp*32 + g*8 + jj] = (w[2kp], w[2kp+1])
#pragma unroll 4
    for (int it = 0; it < 64; ++it) {
        int idx = tid + (it << 8);
        int kp = idx >> 5, lc = idx & 31;
        int g = lc & 3, jj = lc >> 2;
        float w0 = g_whh[(size_t)(2 * kp) * 4096 + (p << 5) + lc];
        float w1 = g_whh[(size_t)(2 * kp + 1) * 4096 + (p << 5) + lc];
        sW[(kp << 5) + (g << 3) + jj] = make_float2(w0, w1);
    }
    float c0 = 0.f, c1 = 0.f;
    __syncthreads();

    for (int t = 0; t < 512; ++t) {
        const float *hsrc = g_h[t & 1];
        float *hdst = g_h[(t + 1) & 1];
        float mu = __ldg(mean + t * 1024 + j);
        float iss = __ldg(scale + t * 1024 + j) * rsqrtf(__ldg(var + t * 1024 + j) + 1e-5f);
        float off = __ldg(offs + t * 1024 + j);

        unsigned long long acc[2][4];
        {
            const float4 x0 = *(const float4 *)&g_xp[((size_t)t * 64 + r0) * 4096 +
                                                     (p << 5) + (jp << 2)];
            const float4 x1 = *(const float4 *)&g_xp[((size_t)t * 64 + r1) * 4096 +
                                                     (p << 5) + (jp << 2)];
            acc[0][0] = pk(x0.x, 0.f); acc[0][1] = pk(x0.y, 0.f);
            acc[0][2] = pk(x0.z, 0.f); acc[0][3] = pk(x0.w, 0.f);
            acc[1][0] = pk(x1.x, 0.f); acc[1][1] = pk(x1.y, 0.f);
            acc[1][2] = pk(x1.z, 0.f); acc[1][3] = pk(x1.w, 0.f);
        }

        float4 pf[4];
#pragma unroll
        for (int ii = 0; ii < 4; ++ii) {
            int lin = tid + (ii << 8);
            pf[ii] = __ldcg((const float4 *)&hsrc[(lin >> 4) * 1024 + ((lin & 15) << 2)]);
        }
        int cur = 0;
        for (int ch = 0; ch < 16; ++ch) {
#pragma unroll
            for (int ii = 0; ii < 4; ++ii) {
                int lin = tid + (ii << 8);
                float2 *d = &sH[cur * 64 * HS + (lin >> 4) * HS + ((lin & 15) << 1)];
                d[0] = make_float2(pf[ii].x, pf[ii].y);
                d[1] = make_float2(pf[ii].z, pf[ii].w);
            }
            __syncthreads();
            if (ch < 15) {
                int kb = (ch + 1) << 6;
#pragma unroll
                for (int ii = 0; ii < 4; ++ii) {
                    int lin = tid + (ii << 7 << 1);
                    pf[ii] = __ldcg(
                        (const float4 *)&hsrc[(lin >> 4) * 1024 + kb + ((lin & 15) << 2)]);
                }
            }
            const float2 *wb = sW + (ch << 10) + jp;  // (ch*32 kpairs)*32
            const float2 *hb = sH + cur * 64 * HS;
#pragma unroll 8
            for (int kk = 0; kk < 32; ++kk) {
                unsigned long long w0 = *(const unsigned long long *)&wb[(kk << 5)];
                unsigned long long w1 = *(const unsigned long long *)&wb[(kk << 5) + 8];
                unsigned long long w2 = *(const unsigned long long *)&wb[(kk << 5) + 16];
                unsigned long long w3 = *(const unsigned long long *)&wb[(kk << 5) + 24];
                unsigned long long h0 = *(const unsigned long long *)&hb[r0 * HS + kk];
                unsigned long long h1 = *(const unsigned long long *)&hb[r1 * HS + kk];
                ffma2(acc[0][0], h0, w0); ffma2(acc[0][1], h0, w1);
                ffma2(acc[0][2], h0, w2); ffma2(acc[0][3], h0, w3);
                ffma2(acc[1][0], h1, w0); ffma2(acc[1][1], h1, w1);
                ffma2(acc[1][2], h1, w2); ffma2(acc[1][3], h1, w3);
            }
            cur ^= 1;
        }

        float s0[4], s1[4];
#pragma unroll
        for (int g = 0; g < 4; ++g) {
            float lo, hi;
            upk(acc[0][g], lo, hi); s0[g] = lo + hi;
            upk(acc[1][g], lo, hi); s1[g] = lo + hi;
        }
        // gate order: f, i, o, gbar
        c0 = sigm(s0[0] + 1.f) * c0 + sigm(s0[1]) * tanhf(s0[3]);
        c1 = sigm(s1[0] + 1.f) * c1 + sigm(s1[1]) * tanhf(s1[3]);
        float h0 = sigm(s0[2]) * tanhf((c0 - mu) * iss + off);
        float h1 = sigm(s1[2]) * tanhf((c1 - mu) * iss + off);
        hdst[r0 * 1024 + j] = h0;
        hdst[r1 * 1024 + j] = h1;
        if (t == 511) {
            out[r0 * 1024 + j] = h0;
            out[r1 * 1024 + j] = h1;
        }

        // grid barrier (release/acquire, monotonic counter)
        __syncthreads();
        if (tid == 0) {
            asm volatile("red.release.gpu.add.u32 [%0], %1;" ::"l"(&g_cnt), "r"(1u)
                         : "memory");
            unsigned target = (unsigned)(t + 1) * NB, x;
            do {
                asm volatile("ld.acquire.gpu.u32 %0, [%1];" : "=r"(x) : "l"(&g_cnt) : "memory");
            } while (x < target);
        }
        __syncthreads();
    }
}

extern "C" void kernel_launch(void *const *d_in, const int *in_sizes, int n_in, void *d_out,
                              int out_size) {
    const float *X = (const float *)d_in[0];
    const float *wxh = (const float *)d_in[1];
    const float *whh = (const float *)d_in[2];
    const float *bias = (const float *)d_in[3];
    const float *scale = (const float *)d_in[4];
    const float *offs = (const float *)d_in[5];
    const float *mean = (const float *)d_in[6];
    const float *var = (const float *)d_in[7];

    int smem = (16384 + 2 * 64 * HS) * (int)sizeof(float2);  // 164,864 B
    cudaFuncSetAttribute(recur_kernel, cudaFuncAttributeMaxDynamicSharedMemorySize, smem);

    pack_kernel<<<256, 256>>>(wxh, whh, bias);
    proj_kernel<<<dim3(32, 512), 256>>>(X);
    recur_kernel<<<NB, 256, smem>>>(scale, offs, mean, var, (float *)d_out);
}

// round 13
// speedup vs baseline: 1.0306x; 1.0306x over previous
#include <cuda_runtime.h>
#include <cstddef>

#define NB 128
#define WST 514          // sW row stride in float2 (4-bank shift/row)
#define HST 66           // sH row stride in float2 (16B aligned, 4-bank shift/row)
#define SH_BUF (64 * HST)

__device__ float g_xp[(size_t)512 * 64 * 4096];  // [t][b][pcol]
__device__ float g_wxh[512 * 4096];              // [k][pcol], pcol=j*4+gate
__device__ float g_bias[4096];
__device__ float g_h[2][64 * 1024];
__device__ unsigned g_cnt;

__device__ __forceinline__ void ffma2(unsigned long long &a, unsigned long long x,
                                      unsigned long long y) {
    asm volatile("fma.rn.f32x2 %0, %1, %2, %0;" : "+l"(a) : "l"(x), "l"(y));
}
__device__ __forceinline__ unsigned long long pk(float x, float y) {
    unsigned long long r;
    asm("mov.b64 %0,{%1,%2};" : "=l"(r) : "f"(x), "f"(y));
    return r;
}
__device__ __forceinline__ void upk(unsigned long long v, float &x, float &y) {
    asm("mov.b64 {%0,%1},%2;" : "=f"(x), "=f"(y) : "l"(v));
}
__device__ __forceinline__ float sigm(float x) { return 1.f / (1.f + expf(-x)); }

// ---------------- pack: permute W_XH/bias to pcol = j*4+gate; reset state ----------------
__global__ void pack_kernel(const float *__restrict__ wxh, const float *__restrict__ bias) {
    int stride = gridDim.x * blockDim.x;
    int i0 = blockIdx.x * blockDim.x + threadIdx.x;
    for (int idx = i0; idx < 512 * 4096; idx += stride) {
        int k = idx >> 12, pcol = idx & 4095;
        int src = ((pcol & 3) << 10) + (pcol >> 2);  // gate*1024 + j
        g_wxh[idx] = wxh[(size_t)k * 4096 + src];
        if (k == 0) g_bias[pcol] = bias[src];
    }
    for (int idx = i0; idx < 2 * 64 * 1024; idx += stride) (&g_h[0][0])[idx] = 0.f;
    if (i0 == 0) g_cnt = 0u;
}

// ---------------- projection: g_xp[t][b][:] = X[b,t,:] @ Wp + bias ----------------
__global__ void __launch_bounds__(256, 2) proj_kernel(const float *__restrict__ X) {
    __shared__ float As[2][16][66];
    __shared__ float Bs[2][16][132];
    int tid = threadIdx.x;
    int tx = tid & 15, ty = tid >> 4;
    int n0 = blockIdx.x * 128, m0 = blockIdx.y * 64;

    unsigned long long acc[4][4];
#pragma unroll
    for (int i = 0; i < 4; ++i)
#pragma unroll
        for (int q = 0; q < 4; ++q) acc[i][q] = 0ull;

    int am = tid >> 2, ak = (tid & 3) << 2;
    int bk = tid >> 5, bc = (tid & 31) << 2;

    float4 Av, Bv0, Bv1;
    Av = *(const float4 *)(X + (size_t)(m0 + am) * 512 + ak);
    Bv0 = *(const float4 *)(g_wxh + (size_t)bk * 4096 + n0 + bc);
    Bv1 = *(const float4 *)(g_wxh + (size_t)(bk + 8) * 4096 + n0 + bc);
    As[0][ak + 0][am] = Av.x; As[0][ak + 1][am] = Av.y;
    As[0][ak + 2][am] = Av.z; As[0][ak + 3][am] = Av.w;
    *(float4 *)&Bs[0][bk][bc] = Bv0;
    *(float4 *)&Bs[0][bk + 8][bc] = Bv1;
    __syncthreads();

    for (int kt = 0; kt < 32; ++kt) {
        int cur = kt & 1;
        if (kt < 31) {
            int kb = (kt + 1) << 4;
            Av = *(const float4 *)(X + (size_t)(m0 + am) * 512 + kb + ak);
            Bv0 = *(const float4 *)(g_wxh + (size_t)(kb + bk) * 4096 + n0 + bc);
            Bv1 = *(const float4 *)(g_wxh + (size_t)(kb + bk + 8) * 4096 + n0 + bc);
        }
#pragma unroll
        for (int k = 0; k < 16; ++k) {
            unsigned long long a[4], b[4];
#pragma unroll
            for (int i = 0; i < 4; ++i) {
                float av = As[cur][k][(ty << 2) + i];
                a[i] = pk(av, av);
            }
#pragma unroll
            for (int q = 0; q < 4; ++q)
                b[q] = *(const unsigned long long *)&Bs[cur][k][2 * tx + 32 * q];
#pragma unroll
            for (int i = 0; i < 4; ++i)
#pragma unroll
                for (int q = 0; q < 4; ++q) ffma2(acc[i][q], a[i], b[q]);
        }
        if (kt < 31) {
            int nb = cur ^ 1;
            As[nb][ak + 0][am] = Av.x; As[nb][ak + 1][am] = Av.y;
            As[nb][ak + 2][am] = Av.z; As[nb][ak + 3][am] = Av.w;
            *(float4 *)&Bs[nb][bk][bc] = Bv0;
            *(float4 *)&Bs[nb][bk + 8][bc] = Bv1;
        }
        __syncthreads();
    }

    float2 bb[4];
#pragma unroll
    for (int q = 0; q < 4; ++q) bb[q] = *(const float2 *)&g_bias[n0 + 2 * tx + 32 * q];
#pragma unroll
    for (int i = 0; i < 4; ++i) {
        int m = m0 + (ty << 2) + i;
        int t = m & 511, b = m >> 9;
        size_t base = ((size_t)t * 64 + b) * 4096 + n0 + 2 * tx;
#pragma unroll
        for (int q = 0; q < 4; ++q) {
            float lo, hi;
            upk(acc[i][q], lo, hi);
            *(float2 *)&g_xp[base + 32 * q] = make_float2(lo + bb[q].x, hi + bb[q].y);
        }
    }
}

// ---------------- persistent recurrence: 128 blocks x 256 threads ----------------
// Block p owns j in [8p,8p+8). Thread (rp 0..31, jp 0..7): rows {2rp,2rp+1}, one j,
// all 4 gates. W slice in SMEM (layout [g*8+jp][kp] float2, stride WST) read with
// LDS.128 (2 k-pairs per load). h in 128-k chunks, double-buffered, k-pair packed
// ([row][kp], stride HST), 8 syncs/step. c-state in regs. 1 grid barrier/step.
__global__ void __launch_bounds__(256, 1)
recur_kernel(const float *__restrict__ whh, const float *__restrict__ scale,
             const float *__restrict__ offs, const float *__restrict__ mean,
             const float *__restrict__ var, float *__restrict__ out) {
    extern __shared__ float2 sm[];
    float2 *sW = sm;               // 32 x WST
    float2 *sH = sm + 32 * WST;    // 2 x 64 x HST

    int tid = threadIdx.x, p = blockIdx.x;
    int jp = tid & 7, rp = tid >> 3;
    int r0 = rp << 1, r1 = r0 + 1;
    int j = (p << 3) + jp;

    // W_HH slice -> SMEM once. Row r = g*8+jj; source col = g*1024 + (p*8+jj).
#pragma unroll 4
    for (int it = 0; it < 64; ++it) {
        int idx = tid + (it << 8);        // 0..16383
        int kp = idx & 511, r = idx >> 9; // r 0..31
        int g = r >> 3, jj = r & 7;
        int col = (g << 10) + (p << 3) + jj;
        sW[r * WST + kp] = make_float2(whh[(size_t)(2 * kp) * 4096 + col],
                                       whh[(size_t)(2 * kp + 1) * 4096 + col]);
    }
    float c0 = 0.f, c1 = 0.f;
    __syncthreads();

    for (int t = 0; t < 512; ++t) {
        const float *hsrc = g_h[t & 1];
        float *hdst = g_h[(t + 1) & 1];
        float mu = __ldg(mean + t * 1024 + j);
        float iss = __ldg(scale + t * 1024 + j) * rsqrtf(__ldg(var + t * 1024 + j) + 1e-5f);
        float off = __ldg(offs + t * 1024 + j);

        unsigned long long acc[2][4];
        {
            const float4 x0 = *(const float4 *)&g_xp[((size_t)t * 64 + r0) * 4096 +
                                                     (p << 5) + (jp << 2)];
            const float4 x1 = *(const float4 *)&g_xp[((size_t)t * 64 + r1) * 4096 +
                                                     (p << 5) + (jp << 2)];
            acc[0][0] = pk(x0.x, 0.f); acc[0][1] = pk(x0.y, 0.f);
            acc[0][2] = pk(x0.z, 0.f); acc[0][3] = pk(x0.w, 0.f);
            acc[1][0] = pk(x1.x, 0.f); acc[1][1] = pk(x1.y, 0.f);
            acc[1][2] = pk(x1.z, 0.f); acc[1][3] = pk(x1.w, 0.f);
        }

        // prefetch chunk 0 (128 k = 32 float4 per row)
        float4 pf[8];
#pragma unroll
        for (int ii = 0; ii < 8; ++ii) {
            int lin = tid + (ii << 8);
            pf[ii] = __ldcg((const float4 *)&hsrc[(lin >> 5) * 1024 + ((lin & 31) << 2)]);
        }
        int cur = 0;
        for (int ch = 0; ch < 8; ++ch) {
            // store chunk: float4 = kp pair {2q, 2q+1}, one STS.128
#pragma unroll
            for (int ii = 0; ii < 8; ++ii) {
                int lin = tid + (ii << 8);
                *(float4 *)&sH[cur * SH_BUF + (lin >> 5) * HST + ((lin & 31) << 1)] = pf[ii];
            }
            __syncthreads();
            if (ch < 7) {
                int kb = (ch + 1) << 7;
#pragma unroll
                for (int ii = 0; ii < 8; ++ii) {
                    int lin = tid + (ii << 8);
                    pf[ii] = __ldcg(
                        (const float4 *)&hsrc[(lin >> 5) * 1024 + kb + ((lin & 31) << 2)]);
                }
            }
            const float2 *wb = sW + (ch << 6);       // + r*WST + kp2*2
            const float2 *hb = sH + cur * SH_BUF;
#pragma unroll 8
            for (int kp2 = 0; kp2 < 32; ++kp2) {
                ulonglong2 h0 = *(const ulonglong2 *)&hb[r0 * HST + (kp2 << 1)];
                ulonglong2 h1 = *(const ulonglong2 *)&hb[r1 * HST + (kp2 << 1)];
#pragma unroll
                for (int g = 0; g < 4; ++g) {
                    ulonglong2 w = *(const ulonglong2 *)&wb[((g << 3) + jp) * WST + (kp2 << 1)];
                    ffma2(acc[0][g], h0.x, w.x);
                    ffma2(acc[0][g], h0.y, w.y);
                    ffma2(acc[1][g], h1.x, w.x);
                    ffma2(acc[1][g], h1.y, w.y);
                }
            }
            cur ^= 1;
        }

        float s0[4], s1[4];
#pragma unroll
        for (int g = 0; g < 4; ++g) {
            float lo, hi;
            upk(acc[0][g], lo, hi); s0[g] = lo + hi;
            upk(acc[1][g], lo, hi); s1[g] = lo + hi;
        }
        // gate order: f, i, o, gbar
        c0 = sigm(s0[0] + 1.f) * c0 + sigm(s0[1]) * tanhf(s0[3]);
        c1 = sigm(s1[0] + 1.f) * c1 + sigm(s1[1]) * tanhf(s1[3]);
        float h0 = sigm(s0[2]) * tanhf((c0 - mu) * iss + off);
        float h1 = sigm(s1[2]) * tanhf((c1 - mu) * iss + off);
        hdst[r0 * 1024 + j] = h0;
        hdst[r1 * 1024 + j] = h1;
        if (t == 511) {
            out[r0 * 1024 + j] = h0;
            out[r1 * 1024 + j] = h1;
        }

        // grid barrier (release/acquire, monotonic counter)
        __syncthreads();
        if (tid == 0) {
            asm volatile("red.release.gpu.add.u32 [%0], %1;" ::"l"(&g_cnt), "r"(1u)
                         : "memory");
            unsigned target = (unsigned)(t + 1) * NB, x;
            do {
                asm volatile("ld.acquire.gpu.u32 %0, [%1];" : "=r"(x) : "l"(&g_cnt) : "memory");
            } while (x < target);
        }
        __syncthreads();
    }
}

extern "C" void kernel_launch(void *const *d_in, const int *in_sizes, int n_in, void *d_out,
                              int out_size) {
    const float *X = (const float *)d_in[0];
    const float *wxh = (const float *)d_in[1];
    const float *whh = (const float *)d_in[2];
    const float *bias = (const float *)d_in[3];
    const float *scale = (const float *)d_in[4];
    const float *offs = (const float *)d_in[5];
    const float *mean = (const float *)d_in[6];
    const float *var = (const float *)d_in[7];

    int smem = (32 * WST + 2 * SH_BUF) * (int)sizeof(float2);  // 199,168 B
    cudaFuncSetAttribute(recur_kernel, cudaFuncAttributeMaxDynamicSharedMemorySize, smem);

    pack_kernel<<<256, 256>>>(wxh, bias);
    proj_kernel<<<dim3(32, 512), 256>>>(X);
    recur_kernel<<<NB, 256, smem>>>(whh, scale, offs, mean, var, (float *)d_out);
}